// round 3
// baseline (speedup 1.0000x reference)
#include <cuda_runtime.h>
#include <math.h>

#define BB   32
#define HH   128
#define WWD  128
#define CC   80
#define DHH  10
#define NHH  8
#define NTOK (BB*HH*WWD)      // 524288
#define NWIN 8192             // windows per attention layer (both modes)

// ---- scratch (allocation-free: device globals) ----
__device__ float g_t1[(size_t)NTOK * CC];
__device__ float g_t2[(size_t)NTOK * CC];

__device__ __forceinline__ float warp_sum(float v) {
    v += __shfl_xor_sync(0xffffffffu, v, 16);
    v += __shfl_xor_sync(0xffffffffu, v, 8);
    v += __shfl_xor_sync(0xffffffffu, v, 4);
    v += __shfl_xor_sync(0xffffffffu, v, 2);
    v += __shfl_xor_sync(0xffffffffu, v, 1);
    return v;
}

// token t (0..63) inside window (b, r0, c0) -> global element base offset
template<bool GRIDMODE>
__device__ __forceinline__ size_t tok_base(int b, int r0, int c0, int t) {
    int i = t >> 3, j = t & 7;
    int hh, ww;
    if (!GRIDMODE) { hh = r0 * 8 + i;  ww = c0 * 8 + j;  }   // 8x8 window
    else           { hh = i * 16 + r0; ww = j * 16 + c0; }   // 8x8 grid (stride 16)
    return ((size_t)((b * HH + hh) * WWD + ww)) * CC;
}

// ============================================================================
// Attention kernel: one CTA per 64-token window.
//   x -> l2norm -> qkv -> per-head softmax(QK^T/sqrt(d)) V -> proj -> +residual
// smem: xn[64][80], q[64][80], k[64][80], v[64][80]  (80 KB)
// ============================================================================
template<bool GRIDMODE>
__global__ __launch_bounds__(256, 2)
void attn_kernel(const float* __restrict__ xin,
                 const float* __restrict__ wqkv, const float* __restrict__ bqkv,
                 const float* __restrict__ wproj, const float* __restrict__ bproj,
                 float* __restrict__ yout)
{
    extern __shared__ float sm[];
    float* xn = sm;                 // 5120
    float* sq = sm + 5120;          // 5120
    float* sk = sm + 10240;         // 5120
    float* sv = sm + 15360;         // 5120

    const int tid  = threadIdx.x;
    const int lane = tid & 31;
    const int wid  = tid >> 5;

    const int wblk = blockIdx.x;
    const int b    = wblk >> 8;
    const int rem  = wblk & 255;
    const int r0   = rem >> 4;
    const int c0   = rem & 15;

    // ---- load + l2norm (each warp: tokens wid, wid+8, ...) ----
    for (int t = wid; t < 64; t += 8) {
        const float* p = xin + tok_base<GRIDMODE>(b, r0, c0, t);
        float v0 = p[lane];
        float v1 = p[lane + 32];
        float v2 = (lane < 16) ? p[lane + 64] : 0.f;
        float s  = warp_sum(v0*v0 + v1*v1 + v2*v2);
        float inv = 1.f / fmaxf(sqrtf(s), 1e-12f);
        float* xr = xn + t * CC;
        xr[lane]      = v0 * inv;
        xr[lane + 32] = v1 * inv;
        if (lane < 16) xr[lane + 64] = v2 * inv;
    }
    __syncthreads();

    // ---- qkv = xn @ Wqkv + b : one output column (of 240) per thread ----
    if (tid < 240) {
        const int c  = tid;
        const int hd = c / 30;
        const int s3 = (c % 30) / 10;
        const int d  = c % 10;
        float* dst = (s3 == 0) ? sq : (s3 == 1) ? sk : sv;
        const int dco = hd * DHH + d;
        const float bias = bqkv[c];
        #pragma unroll
        for (int tb = 0; tb < 2; ++tb) {          // 2 blocks of 32 tokens
            float acc[32];
            #pragma unroll
            for (int r = 0; r < 32; ++r) acc[r] = bias;
            const float* wp = wqkv + c;
            const float* xr = xn + tb * 32 * CC;
            #pragma unroll 4
            for (int j = 0; j < CC; ++j) {
                float wv = __ldg(wp + j * 240);
                #pragma unroll
                for (int r = 0; r < 32; ++r) acc[r] += xr[r * CC + j] * wv;
            }
            #pragma unroll
            for (int r = 0; r < 32; ++r) dst[(tb * 32 + r) * CC + dco] = acc[r];
        }
    }
    __syncthreads();

    // ---- attention: one head per warp, 2 queries per lane, online softmax ----
    {
        const int hd = wid;
        const float* qb = sq + hd * DHH;
        const float* kb = sk + hd * DHH;
        const float* vb = sv + hd * DHH;
        float q0[10], q1[10], o0[10], o1[10];
        #pragma unroll
        for (int d = 0; d < 10; ++d) {
            q0[d] = qb[lane * CC + d];
            q1[d] = qb[(lane + 32) * CC + d];
            o0[d] = 0.f; o1[d] = 0.f;
        }
        float m0 = -1e30f, m1 = -1e30f, l0 = 0.f, l1 = 0.f;
        const float scale = 0.31622776601683794f;   // 10^-0.5
        for (int kk = 0; kk < 64; ++kk) {
            float kv[10], vv[10];
            #pragma unroll
            for (int d = 0; d < 10; ++d) { kv[d] = kb[kk*CC + d]; vv[d] = vb[kk*CC + d]; }
            float s0 = 0.f, s1 = 0.f;
            #pragma unroll
            for (int d = 0; d < 10; ++d) { s0 += q0[d]*kv[d]; s1 += q1[d]*kv[d]; }
            s0 *= scale; s1 *= scale;

            float nm0 = fmaxf(m0, s0);
            float cf0 = __expf(m0 - nm0);
            float p0  = __expf(s0 - nm0);
            l0 = l0 * cf0 + p0;
            #pragma unroll
            for (int d = 0; d < 10; ++d) o0[d] = o0[d] * cf0 + p0 * vv[d];
            m0 = nm0;

            float nm1 = fmaxf(m1, s1);
            float cf1 = __expf(m1 - nm1);
            float p1  = __expf(s1 - nm1);
            l1 = l1 * cf1 + p1;
            #pragma unroll
            for (int d = 0; d < 10; ++d) o1[d] = o1[d] * cf1 + p1 * vv[d];
            m1 = nm1;
        }
        const float il0 = 1.f / l0, il1 = 1.f / l1;
        float* ob = sq + hd * DHH;   // q slice no longer needed (per-head private)
        #pragma unroll
        for (int d = 0; d < 10; ++d) {
            ob[lane * CC + d]        = o0[d] * il0;
            ob[(lane + 32) * CC + d] = o1[d] * il1;
        }
    }
    __syncthreads();

    // ---- proj + residual + scatter-back: warp handles 8 tokens, 3 col groups ----
    {
        const float* ob = sq + wid * 8 * CC;
        #pragma unroll
        for (int cb = 0; cb < 3; ++cb) {
            int c = lane + cb * 32;
            if (c < CC) {
                float acc[8];
                float bias = bproj[c];
                #pragma unroll
                for (int r = 0; r < 8; ++r) acc[r] = bias;
                #pragma unroll 4
                for (int j = 0; j < CC; ++j) {
                    float wv = __ldg(wproj + j * CC + c);
                    #pragma unroll
                    for (int r = 0; r < 8; ++r) acc[r] += ob[r * CC + j] * wv;
                }
                #pragma unroll
                for (int r = 0; r < 8; ++r) {
                    int t = wid * 8 + r;
                    yout[tok_base<GRIDMODE>(b, r0, c0, t) + c] = xn[t * CC + c] + acc[r];
                }
            }
        }
    }
}

// ============================================================================
// MLP kernel: one CTA per 64 contiguous tokens.
//   x -> l2norm -> h=relu(x@W1) -> h2=(relu?)(h@W2+b2) -> x + h2*gamma
// smem: xn[64][80] + h[64][320]  (100 KB)
// ============================================================================
template<bool RELU2>
__global__ __launch_bounds__(256, 2)
void mlp_kernel(const float* __restrict__ xin,
                const float* __restrict__ w1,
                const float* __restrict__ w2,
                const float* __restrict__ b2,
                const float* __restrict__ gamma,
                float* __restrict__ yout)
{
    extern __shared__ float sm[];
    float* xn = sm;            // 5120
    float* hb = sm + 5120;     // 20480

    const int tid  = threadIdx.x;
    const int lane = tid & 31;
    const int wid  = tid >> 5;
    const size_t base = (size_t)blockIdx.x * 64 * CC;

    // ---- load + l2norm ----
    for (int t = wid; t < 64; t += 8) {
        const float* p = xin + base + (size_t)t * CC;
        float v0 = p[lane];
        float v1 = p[lane + 32];
        float v2 = (lane < 16) ? p[lane + 64] : 0.f;
        float s  = warp_sum(v0*v0 + v1*v1 + v2*v2);
        float inv = 1.f / fmaxf(sqrtf(s), 1e-12f);
        float* xr = xn + t * CC;
        xr[lane]      = v0 * inv;
        xr[lane + 32] = v1 * inv;
        if (lane < 16) xr[lane + 64] = v2 * inv;
    }
    __syncthreads();

    // ---- h = relu(xn @ W1), 320 cols; warp handles 8 tokens, 10 col groups ----
    {
        const float* xr = xn + wid * 8 * CC;
        float* hr = hb + wid * 8 * 320;
        #pragma unroll
        for (int cb = 0; cb < 10; ++cb) {
            const int c = lane + cb * 32;
            float acc[8];
            #pragma unroll
            for (int r = 0; r < 8; ++r) acc[r] = 0.f;
            #pragma unroll 4
            for (int j = 0; j < CC; ++j) {
                float wv = __ldg(w1 + j * 320 + c);
                #pragma unroll
                for (int r = 0; r < 8; ++r) acc[r] += xr[r * CC + j] * wv;
            }
            #pragma unroll
            for (int r = 0; r < 8; ++r) hr[r * 320 + c] = fmaxf(acc[r], 0.f);
        }
    }
    __syncthreads();

    // ---- out = xn + act(h @ W2 + b2) * gamma ----
    {
        const float* hr = hb + wid * 8 * 320;
        #pragma unroll
        for (int cb = 0; cb < 3; ++cb) {
            const int c = lane + cb * 32;
            if (c < CC) {
                float acc[8];
                const float bias = b2[c];
                #pragma unroll
                for (int r = 0; r < 8; ++r) acc[r] = bias;
                #pragma unroll 4
                for (int j = 0; j < 320; ++j) {
                    float wv = __ldg(w2 + j * CC + c);
                    #pragma unroll
                    for (int r = 0; r < 8; ++r) acc[r] += hr[r * 320 + j] * wv;
                }
                const float g = gamma[c];
                #pragma unroll
                for (int r = 0; r < 8; ++r) {
                    float v = acc[r];
                    if (RELU2) v = fmaxf(v, 0.f);
                    const int t = wid * 8 + r;
                    yout[base + (size_t)t * CC + c] = xn[t * CC + c] + v * g;
                }
            }
        }
    }
}

// ============================================================================
extern "C" void kernel_launch(void* const* d_in, const int* in_sizes, int n_in,
                              void* d_out, int out_size)
{
    const float* x       = (const float*)d_in[0];
    const float* bw_qkv  = (const float*)d_in[1];
    const float* bb_qkv  = (const float*)d_in[2];
    const float* bw_proj = (const float*)d_in[3];
    const float* bb_proj = (const float*)d_in[4];
    const float* b_gamma = (const float*)d_in[5];
    const float* bw_mlp1 = (const float*)d_in[6];
    const float* bw_mlp2 = (const float*)d_in[7];
    const float* bb_mlp2 = (const float*)d_in[8];
    const float* gw_qkv  = (const float*)d_in[9];
    const float* gb_qkv  = (const float*)d_in[10];
    const float* gw_proj = (const float*)d_in[11];
    const float* gb_proj = (const float*)d_in[12];
    const float* g_gamma = (const float*)d_in[13];
    const float* gw_mlp1 = (const float*)d_in[14];
    const float* gw_mlp2 = (const float*)d_in[15];
    const float* gb_mlp2 = (const float*)d_in[16];
    float* out = (float*)d_out;

    float *t1 = nullptr, *t2 = nullptr;
    cudaGetSymbolAddress((void**)&t1, g_t1);
    cudaGetSymbolAddress((void**)&t2, g_t2);

    const int ATTN_SMEM = 4 * 64 * CC * (int)sizeof(float);          // 81920
    const int MLP_SMEM  = (64 * CC + 64 * 320) * (int)sizeof(float); // 102400

    static bool attrs_set = false;
    if (!attrs_set) {
        cudaFuncSetAttribute(attn_kernel<false>, cudaFuncAttributeMaxDynamicSharedMemorySize, ATTN_SMEM);
        cudaFuncSetAttribute(attn_kernel<true>,  cudaFuncAttributeMaxDynamicSharedMemorySize, ATTN_SMEM);
        cudaFuncSetAttribute(mlp_kernel<true>,   cudaFuncAttributeMaxDynamicSharedMemorySize, MLP_SMEM);
        cudaFuncSetAttribute(mlp_kernel<false>,  cudaFuncAttributeMaxDynamicSharedMemorySize, MLP_SMEM);
        attrs_set = true;
    }

    const int NB_MLP = NTOK / 64;   // 8192

    // block_sa
    attn_kernel<false><<<NWIN, 256, ATTN_SMEM>>>(x,  bw_qkv, bb_qkv, bw_proj, bb_proj, t1);
    mlp_kernel<true><<<NB_MLP, 256, MLP_SMEM>>>(t1, bw_mlp1, bw_mlp2, bb_mlp2, b_gamma, t2);
    // grid_sa
    attn_kernel<true><<<NWIN, 256, ATTN_SMEM>>>(t2, gw_qkv, gb_qkv, gw_proj, gb_proj, t1);
    mlp_kernel<false><<<NB_MLP, 256, MLP_SMEM>>>(t1, gw_mlp1, gw_mlp2, gb_mlp2, g_gamma, out);
}

// round 4
// speedup vs baseline: 1.6109x; 1.6109x over previous
#include <cuda_runtime.h>
#include <math.h>

#define BB   32
#define HH   128
#define WWD  128
#define CC   80
#define DHH  10
#define NHH  8
#define NTOK (BB*HH*WWD)      // 524288
#define NWIN 8192

// ---- scratch (allocation-free: device globals) ----
__device__ float g_t1[(size_t)NTOK * CC];
__device__ float g_t2[(size_t)NTOK * CC];

__device__ __forceinline__ float warp_sum(float v) {
    v += __shfl_xor_sync(0xffffffffu, v, 16);
    v += __shfl_xor_sync(0xffffffffu, v, 8);
    v += __shfl_xor_sync(0xffffffffu, v, 4);
    v += __shfl_xor_sync(0xffffffffu, v, 2);
    v += __shfl_xor_sync(0xffffffffu, v, 1);
    return v;
}

template<bool GRIDMODE>
__device__ __forceinline__ size_t tok_base(int b, int r0, int c0, int t) {
    int i = t >> 3, j = t & 7;
    int hh, ww;
    if (!GRIDMODE) { hh = r0 * 8 + i;  ww = c0 * 8 + j;  }
    else           { hh = i * 16 + r0; ww = j * 16 + c0; }
    return ((size_t)((b * HH + hh) * WWD + ww)) * CC;
}

// ============================================================================
// Attention kernel: one CTA per 64-token window. smem 80KB, 2 CTAs/SM.
// ============================================================================
template<bool GRIDMODE>
__global__ __launch_bounds__(256, 2)
void attn_kernel(const float* __restrict__ xin,
                 const float* __restrict__ wqkv, const float* __restrict__ bqkv,
                 const float* __restrict__ wproj, const float* __restrict__ bproj,
                 float* __restrict__ yout)
{
    extern __shared__ float sm[];
    float* xn = sm;                 // 64x80
    float* sq = sm + 5120;
    float* sk = sm + 10240;
    float* sv = sm + 15360;

    const int tid  = threadIdx.x;
    const int lane = tid & 31;
    const int wid  = tid >> 5;

    const int wblk = blockIdx.x;
    const int b    = wblk >> 8;
    const int rem  = wblk & 255;
    const int r0   = rem >> 4;
    const int c0   = rem & 15;

    // ---- load + l2norm ----
    for (int t = wid; t < 64; t += 8) {
        const float* p = xin + tok_base<GRIDMODE>(b, r0, c0, t);
        float v0 = p[lane];
        float v1 = p[lane + 32];
        float v2 = (lane < 16) ? p[lane + 64] : 0.f;
        float s  = warp_sum(v0*v0 + v1*v1 + v2*v2);
        float inv = 1.f / fmaxf(sqrtf(s), 1e-12f);
        float* xr = xn + t * CC;
        xr[lane]      = v0 * inv;
        xr[lane + 32] = v1 * inv;
        if (lane < 16) xr[lane + 64] = v2 * inv;
    }
    __syncthreads();

    // ---- qkv = xn @ Wqkv + b : warp -> 8 tokens, thread -> 8 cols (2 halves of 4)
    {
        const float* xr = xn + wid * 8 * CC;
        #pragma unroll 1
        for (int half = 0; half < 2; ++half) {
            int cs[4];
            float acc[8][4];
            #pragma unroll
            for (int g = 0; g < 4; ++g) {
                int c = lane + 32 * (half * 4 + g);
                cs[g] = (c < 240) ? c : 239;          // clamp; junk never stored
                float bias = bqkv[cs[g]];
                #pragma unroll
                for (int r = 0; r < 8; ++r) acc[r][g] = bias;
            }
            #pragma unroll 1
            for (int j4 = 0; j4 < 20; ++j4) {
                float4 xv[8];
                #pragma unroll
                for (int r = 0; r < 8; ++r)
                    xv[r] = *reinterpret_cast<const float4*>(xr + r * CC + j4 * 4);
                const float* xf = reinterpret_cast<const float*>(xv);
                #pragma unroll
                for (int jj = 0; jj < 4; ++jj) {
                    const float* wrow = wqkv + (j4 * 4 + jj) * 240;
                    float wv[4];
                    #pragma unroll
                    for (int g = 0; g < 4; ++g) wv[g] = __ldg(wrow + cs[g]);
                    #pragma unroll
                    for (int g = 0; g < 4; ++g)
                        #pragma unroll
                        for (int r = 0; r < 8; ++r)
                            acc[r][g] = fmaf(xf[r * 4 + jj], wv[g], acc[r][g]);
                }
            }
            #pragma unroll
            for (int g = 0; g < 4; ++g) {
                int c = lane + 32 * (half * 4 + g);
                if (c < 240) {
                    int hd = c / 30, rm = c % 30, s3 = rm / 10, d = rm % 10;
                    float* dst = ((s3 == 0) ? sq : (s3 == 1) ? sk : sv) + hd * DHH + d;
                    #pragma unroll
                    for (int r = 0; r < 8; ++r)
                        dst[(wid * 8 + r) * CC] = acc[r][g];
                }
            }
        }
    }
    __syncthreads();

    // ---- attention: one head per warp, 2 queries per lane, online softmax ----
    {
        const int hd = wid;
        const float* qb = sq + hd * DHH;
        const float* kb = sk + hd * DHH;
        const float* vb = sv + hd * DHH;
        float q0[10], q1[10], o0[10], o1[10];
        #pragma unroll
        for (int d = 0; d < 10; ++d) {
            q0[d] = qb[lane * CC + d];
            q1[d] = qb[(lane + 32) * CC + d];
            o0[d] = 0.f; o1[d] = 0.f;
        }
        float m0 = -1e30f, m1 = -1e30f, l0 = 0.f, l1 = 0.f;
        const float scale = 0.31622776601683794f;
        #pragma unroll 1
        for (int kk = 0; kk < 64; ++kk) {
            float kv[10], vv[10];
            #pragma unroll
            for (int d2 = 0; d2 < 5; ++d2) {
                float2 kt = *reinterpret_cast<const float2*>(kb + kk * CC + d2 * 2);
                float2 vt = *reinterpret_cast<const float2*>(vb + kk * CC + d2 * 2);
                kv[d2*2] = kt.x; kv[d2*2+1] = kt.y;
                vv[d2*2] = vt.x; vv[d2*2+1] = vt.y;
            }
            float s0 = 0.f, s1 = 0.f;
            #pragma unroll
            for (int d = 0; d < 10; ++d) { s0 = fmaf(q0[d], kv[d], s0); s1 = fmaf(q1[d], kv[d], s1); }
            s0 *= scale; s1 *= scale;

            float nm0 = fmaxf(m0, s0);
            float cf0 = __expf(m0 - nm0);
            float p0  = __expf(s0 - nm0);
            l0 = l0 * cf0 + p0;
            #pragma unroll
            for (int d = 0; d < 10; ++d) o0[d] = fmaf(o0[d], cf0, p0 * vv[d]);
            m0 = nm0;

            float nm1 = fmaxf(m1, s1);
            float cf1 = __expf(m1 - nm1);
            float p1  = __expf(s1 - nm1);
            l1 = l1 * cf1 + p1;
            #pragma unroll
            for (int d = 0; d < 10; ++d) o1[d] = fmaf(o1[d], cf1, p1 * vv[d]);
            m1 = nm1;
        }
        const float il0 = 1.f / l0, il1 = 1.f / l1;
        float* ob = sq + hd * DHH;
        #pragma unroll
        for (int d = 0; d < 10; ++d) {
            ob[lane * CC + d]        = o0[d] * il0;
            ob[(lane + 32) * CC + d] = o1[d] * il1;
        }
    }
    __syncthreads();

    // ---- proj + residual + scatter: warp -> 8 tokens, thread -> 3 cols ----
    {
        const float* ob = sq + wid * 8 * CC;
        int cs[3];
        cs[0] = lane; cs[1] = lane + 32; cs[2] = (lane < 16) ? (lane + 64) : 79;
        float acc[8][3];
        #pragma unroll
        for (int g = 0; g < 3; ++g) {
            float bias = bproj[cs[g]];
            #pragma unroll
            for (int r = 0; r < 8; ++r) acc[r][g] = bias;
        }
        #pragma unroll 1
        for (int j4 = 0; j4 < 20; ++j4) {
            float4 ov[8];
            #pragma unroll
            for (int r = 0; r < 8; ++r)
                ov[r] = *reinterpret_cast<const float4*>(ob + r * CC + j4 * 4);
            const float* of = reinterpret_cast<const float*>(ov);
            #pragma unroll
            for (int jj = 0; jj < 4; ++jj) {
                const float* wrow = wproj + (j4 * 4 + jj) * CC;
                float wv[3];
                #pragma unroll
                for (int g = 0; g < 3; ++g) wv[g] = __ldg(wrow + cs[g]);
                #pragma unroll
                for (int g = 0; g < 3; ++g)
                    #pragma unroll
                    for (int r = 0; r < 8; ++r)
                        acc[r][g] = fmaf(of[r * 4 + jj], wv[g], acc[r][g]);
            }
        }
        #pragma unroll
        for (int r = 0; r < 8; ++r) {
            int t = wid * 8 + r;
            size_t base = tok_base<GRIDMODE>(b, r0, c0, t);
            yout[base + cs[0]] = xn[t * CC + cs[0]] + acc[r][0];
            yout[base + cs[1]] = xn[t * CC + cs[1]] + acc[r][1];
            if (lane < 16)
                yout[base + cs[2]] = xn[t * CC + cs[2]] + acc[r][2];
        }
    }
}

// ============================================================================
// MLP kernel: one CTA per 64 contiguous tokens. smem 100KB, 2 CTAs/SM.
// ============================================================================
template<bool RELU2>
__global__ __launch_bounds__(256, 2)
void mlp_kernel(const float* __restrict__ xin,
                const float* __restrict__ w1,
                const float* __restrict__ w2,
                const float* __restrict__ b2,
                const float* __restrict__ gamma,
                float* __restrict__ yout)
{
    extern __shared__ float sm[];
    float* xn = sm;            // 64x80
    float* hb = sm + 5120;     // 64x320

    const int tid  = threadIdx.x;
    const int lane = tid & 31;
    const int wid  = tid >> 5;
    const size_t base = (size_t)blockIdx.x * 64 * CC;

    // ---- load + l2norm ----
    for (int t = wid; t < 64; t += 8) {
        const float* p = xin + base + (size_t)t * CC;
        float v0 = p[lane];
        float v1 = p[lane + 32];
        float v2 = (lane < 16) ? p[lane + 64] : 0.f;
        float s  = warp_sum(v0*v0 + v1*v1 + v2*v2);
        float inv = 1.f / fmaxf(sqrtf(s), 1e-12f);
        float* xr = xn + t * CC;
        xr[lane]      = v0 * inv;
        xr[lane + 32] = v1 * inv;
        if (lane < 16) xr[lane + 64] = v2 * inv;
    }
    __syncthreads();

    // ---- h = relu(xn @ W1): warp -> 8 tokens, thread -> 10 cols (2 halves of 5)
    {
        const float* xr = xn + wid * 8 * CC;
        float* hr = hb + wid * 8 * 320;
        #pragma unroll 1
        for (int half = 0; half < 2; ++half) {
            const int cbase = half * 160 + lane;     // + 32*g, all < 320
            float acc[8][5];
            #pragma unroll
            for (int g = 0; g < 5; ++g)
                #pragma unroll
                for (int r = 0; r < 8; ++r) acc[r][g] = 0.f;
            #pragma unroll 1
            for (int j4 = 0; j4 < 20; ++j4) {
                float4 xv[8];
                #pragma unroll
                for (int r = 0; r < 8; ++r)
                    xv[r] = *reinterpret_cast<const float4*>(xr + r * CC + j4 * 4);
                const float* xf = reinterpret_cast<const float*>(xv);
                #pragma unroll
                for (int jj = 0; jj < 4; ++jj) {
                    const float* wrow = w1 + (j4 * 4 + jj) * 320 + cbase;
                    float wv[5];
                    #pragma unroll
                    for (int g = 0; g < 5; ++g) wv[g] = __ldg(wrow + 32 * g);
                    #pragma unroll
                    for (int g = 0; g < 5; ++g)
                        #pragma unroll
                        for (int r = 0; r < 8; ++r)
                            acc[r][g] = fmaf(xf[r * 4 + jj], wv[g], acc[r][g]);
                }
            }
            #pragma unroll
            for (int g = 0; g < 5; ++g)
                #pragma unroll
                for (int r = 0; r < 8; ++r)
                    hr[r * 320 + cbase + 32 * g] = fmaxf(acc[r][g], 0.f);
        }
    }
    __syncthreads();

    // ---- out = xn + act(h @ W2 + b2) * gamma : warp -> 8 tokens, 3 cols ----
    {
        const float* hr = hb + wid * 8 * 320;
        int cs[3];
        cs[0] = lane; cs[1] = lane + 32; cs[2] = (lane < 16) ? (lane + 64) : 79;
        float acc[8][3];
        #pragma unroll
        for (int g = 0; g < 3; ++g) {
            float bias = b2[cs[g]];
            #pragma unroll
            for (int r = 0; r < 8; ++r) acc[r][g] = bias;
        }
        #pragma unroll 1
        for (int j4 = 0; j4 < 80; ++j4) {
            float4 hv[8];
            #pragma unroll
            for (int r = 0; r < 8; ++r)
                hv[r] = *reinterpret_cast<const float4*>(hr + r * 320 + j4 * 4);
            const float* hf = reinterpret_cast<const float*>(hv);
            #pragma unroll
            for (int jj = 0; jj < 4; ++jj) {
                const float* wrow = w2 + (j4 * 4 + jj) * CC;
                float wv[3];
                #pragma unroll
                for (int g = 0; g < 3; ++g) wv[g] = __ldg(wrow + cs[g]);
                #pragma unroll
                for (int g = 0; g < 3; ++g)
                    #pragma unroll
                    for (int r = 0; r < 8; ++r)
                        acc[r][g] = fmaf(hf[r * 4 + jj], wv[g], acc[r][g]);
            }
        }
        #pragma unroll
        for (int g = 0; g < 3; ++g) {
            const float gm = gamma[cs[g]];
            #pragma unroll
            for (int r = 0; r < 8; ++r) {
                float v = acc[r][g];
                if (RELU2) v = fmaxf(v, 0.f);
                const int t = wid * 8 + r;
                if (g < 2 || lane < 16)
                    yout[base + (size_t)t * CC + cs[g]] = xn[t * CC + cs[g]] + v * gm;
            }
        }
    }
}

// ============================================================================
extern "C" void kernel_launch(void* const* d_in, const int* in_sizes, int n_in,
                              void* d_out, int out_size)
{
    const float* x       = (const float*)d_in[0];
    const float* bw_qkv  = (const float*)d_in[1];
    const float* bb_qkv  = (const float*)d_in[2];
    const float* bw_proj = (const float*)d_in[3];
    const float* bb_proj = (const float*)d_in[4];
    const float* b_gamma = (const float*)d_in[5];
    const float* bw_mlp1 = (const float*)d_in[6];
    const float* bw_mlp2 = (const float*)d_in[7];
    const float* bb_mlp2 = (const float*)d_in[8];
    const float* gw_qkv  = (const float*)d_in[9];
    const float* gb_qkv  = (const float*)d_in[10];
    const float* gw_proj = (const float*)d_in[11];
    const float* gb_proj = (const float*)d_in[12];
    const float* g_gamma = (const float*)d_in[13];
    const float* gw_mlp1 = (const float*)d_in[14];
    const float* gw_mlp2 = (const float*)d_in[15];
    const float* gb_mlp2 = (const float*)d_in[16];
    float* out = (float*)d_out;

    float *t1 = nullptr, *t2 = nullptr;
    cudaGetSymbolAddress((void**)&t1, g_t1);
    cudaGetSymbolAddress((void**)&t2, g_t2);

    const int ATTN_SMEM = 4 * 64 * CC * (int)sizeof(float);          // 81920
    const int MLP_SMEM  = (64 * CC + 64 * 320) * (int)sizeof(float); // 102400

    static bool attrs_set = false;
    if (!attrs_set) {
        cudaFuncSetAttribute(attn_kernel<false>, cudaFuncAttributeMaxDynamicSharedMemorySize, ATTN_SMEM);
        cudaFuncSetAttribute(attn_kernel<true>,  cudaFuncAttributeMaxDynamicSharedMemorySize, ATTN_SMEM);
        cudaFuncSetAttribute(mlp_kernel<true>,   cudaFuncAttributeMaxDynamicSharedMemorySize, MLP_SMEM);
        cudaFuncSetAttribute(mlp_kernel<false>,  cudaFuncAttributeMaxDynamicSharedMemorySize, MLP_SMEM);
        attrs_set = true;
    }

    const int NB_MLP = NTOK / 64;   // 8192

    attn_kernel<false><<<NWIN, 256, ATTN_SMEM>>>(x,  bw_qkv, bb_qkv, bw_proj, bb_proj, t1);
    mlp_kernel<true><<<NB_MLP, 256, MLP_SMEM>>>(t1, bw_mlp1, bw_mlp2, bb_mlp2, b_gamma, t2);
    attn_kernel<true><<<NWIN, 256, ATTN_SMEM>>>(t2, gw_qkv, gb_qkv, gw_proj, gb_proj, t1);
    mlp_kernel<false><<<NB_MLP, 256, MLP_SMEM>>>(t1, gw_mlp1, gw_mlp2, gb_mlp2, g_gamma, out);
}